// round 16
// baseline (speedup 1.0000x reference)
#include <cuda_runtime.h>
#include <cuda_bf16.h>
#include <cstdint>

// inputs [64,2048,64] fp32 -> flat [131072,64]; codebook [1024,64] fp32.
#define N_ROWS   131072
#define D        64
#define K_CODES  1024
#define MTILE    128
#define BLK2     256
#define GRID2    (N_ROWS / MTILE)      // 1024
#define NTILES   (K_CODES / 8)         // 128

#define EX_BLK   256
#define EX_GRID  (N_ROWS / EX_BLK)     // 512

// Output: quantized_ste (8388608) | loss (1) | encoding_indices (131072), fp32
#define LOSS_OFF 8388608
#define IDX_OFF  8388609

#define APAD     144                   // A smem row pitch (bytes): conflict-free

__device__ float g_C[K_CODES];                 // ||c||^2, reference rounding
__device__ uint2 g_bfrag[NTILES * 4 * 32];     // fragment-ordered bf16 HI-only B
__device__ int   g_cnt[N_ROWS];                // 0 = use slots, -1 = coop full scan
__device__ int   g_cidx[N_ROWS * 16];          // candidate slots (sentinel INT_MAX)
__device__ float g_blocksum[EX_GRID];

__device__ __forceinline__ uint32_t packbf(__nv_bfloat16 a, __nv_bfloat16 b) {
    return (uint32_t)__bfloat16_as_ushort(a) | ((uint32_t)__bfloat16_as_ushort(b) << 16);
}
__device__ __forceinline__ __nv_bfloat16 bfhi(float x) { return __float2bfloat16(x); }

// mma.sync m16n8k16 bf16 -> f32 (HMMA; supported on plain sm_103 target)
__device__ __forceinline__ void mma16816(float& c0, float& c1, float& c2, float& c3,
                                         uint32_t a0, uint32_t a1, uint32_t a2, uint32_t a3,
                                         uint32_t b0, uint32_t b1) {
    asm volatile("mma.sync.aligned.m16n8k16.row.col.f32.bf16.bf16.f32 "
                 "{%0,%1,%2,%3}, {%4,%5,%6,%7}, {%8,%9}, {%0,%1,%2,%3};"
                 : "+f"(c0), "+f"(c1), "+f"(c2), "+f"(c3)
                 : "r"(a0), "r"(a1), "r"(a2), "r"(a3), "r"(b0), "r"(b1));
}

__device__ __forceinline__ void ins4(float u, int j,
                                     float& v0, float& v1, float& v2, float& v3,
                                     int& i0, int& i1, int& i2, int& i3) {
    if (u < v3) {
        if (u < v1) {
            if (u < v0) { v3=v2;i3=i2; v2=v1;i2=i1; v1=v0;i1=i0; v0=u;i0=j; }
            else        { v3=v2;i3=i2; v2=v1;i2=i1; v1=u;i1=j; }
        } else {
            if (u < v2) { v3=v2;i3=i2; v2=u;i2=j; }
            else        { v3=u;i3=j; }
        }
    }
}

// ---- kernel 1: ||c||^2 (reference rounding) + fragment-ordered bf16 B -----
__global__ void vq_prep(const float* __restrict__ cb) {
    int e = blockIdx.x * blockDim.x + threadIdx.x;      // 0..16383
    if (e < K_CODES) {
        float s = 0.f;
        #pragma unroll
        for (int k = 0; k < D; k++) {
            float c = cb[e * D + k];
            s = __fadd_rn(s, __fmul_rn(c, c));
        }
        g_C[e] = s;
    }
    // entry (jt, ks, lane): n = lane>>2, kp = lane&3; code = jt*8+n
    int lane = e & 31, ks = (e >> 5) & 3, jt = e >> 7;
    int n = lane >> 2, kp = lane & 3;
    int code = jt * 8 + n;
    int kb = ks * 16 + kp * 2;
    float c0 = cb[code * D + kb],     c1 = cb[code * D + kb + 1];
    float c2 = cb[code * D + kb + 8], c3 = cb[code * D + kb + 9];
    uint2 ent;
    ent.x = packbf(bfhi(c0), bfhi(c1));
    ent.y = packbf(bfhi(c2), bfhi(c3));
    g_bfrag[e] = ent;
}

// ---- kernel 2: single-pass bf16 HMMA score GEMM + certified margin --------
__global__ void __launch_bounds__(BLK2, 2) vq_mma(const float* __restrict__ inp) {
    __shared__ __align__(16) unsigned char sA[128 * APAD];      // hi tile only
    __shared__ float sC2[K_CODES];
    __shared__ float sAn[MTILE];

    const int tid = threadIdx.x;
    const int ctaRow = blockIdx.x * MTILE;

    // Phase 1: threads 0-127 build A tile (bf16 hi) + exact sequential ||x||^2;
    // threads 128-255 stage g_C into smem.
    if (tid < 128) {
        const float4* xr = (const float4*)(inp + (size_t)(ctaRow + tid) * D);
        float A = 0.f;
        unsigned char* rh = sA + tid * APAD;
        #pragma unroll
        for (int i = 0; i < 16; i++) {
            float4 v = xr[i];
            A = __fadd_rn(A, __fmul_rn(v.x, v.x));
            A = __fadd_rn(A, __fmul_rn(v.y, v.y));
            A = __fadd_rn(A, __fmul_rn(v.z, v.z));
            A = __fadd_rn(A, __fmul_rn(v.w, v.w));
            *(uint32_t*)(rh + i * 8)     = packbf(bfhi(v.x), bfhi(v.y));
            *(uint32_t*)(rh + i * 8 + 4) = packbf(bfhi(v.z), bfhi(v.w));
        }
        sAn[tid] = A;
    } else {
        int t = tid - 128;
        #pragma unroll
        for (int i = 0; i < 8; i++) sC2[t * 8 + i] = g_C[t * 8 + i];
    }
    __syncthreads();

    // Phase 2: A fragments for all 4 k-steps resident in registers.
    const int wid = tid >> 5, lane = tid & 31;
    const int mb = wid * 16;
    const int r = lane >> 2, kp = lane & 3;
    uint32_t ah[4][4];
    #pragma unroll
    for (int ks = 0; ks < 4; ks++) {
        uint32_t o = (uint32_t)(mb + r) * APAD + ks * 32 + kp * 4;
        ah[ks][0] = *(const uint32_t*)(sA + o);
        ah[ks][1] = *(const uint32_t*)(sA + o + 8 * APAD);
        ah[ks][2] = *(const uint32_t*)(sA + o + 16);
        ah[ks][3] = *(const uint32_t*)(sA + o + 8 * APAD + 16);
    }

    const float INF = __int_as_float(0x7f800000);
    float v0 = INF, v1 = INF, v2 = INF, v3 = INF;      // rows mb+r
    int   i0 = 0, i1 = 0, i2 = 0, i3 = 0;
    float w0 = INF, w1 = INF, w2 = INF, w3 = INF;      // rows mb+r+8
    int   k0 = 0, k1 = 0, k2 = 0, k3 = 0;

    // Phase 3: stream hi-only fragment B from L2 with register double-buffer.
    const uint2* bf = g_bfrag;
    uint2 bc0 = __ldg(bf + 0 * 32 + lane);
    uint2 bc1 = __ldg(bf + 1 * 32 + lane);
    uint2 bc2 = __ldg(bf + 2 * 32 + lane);
    uint2 bc3 = __ldg(bf + 3 * 32 + lane);

    #pragma unroll 2
    for (int jt = 0; jt < NTILES; jt++) {
        int nt = (jt < NTILES - 1) ? jt + 1 : jt;
        uint2 bn0 = __ldg(bf + (nt * 4 + 0) * 32 + lane);
        uint2 bn1 = __ldg(bf + (nt * 4 + 1) * 32 + lane);
        uint2 bn2 = __ldg(bf + (nt * 4 + 2) * 32 + lane);
        uint2 bn3 = __ldg(bf + (nt * 4 + 3) * 32 + lane);

        float c0 = 0.f, c1 = 0.f, c2 = 0.f, c3 = 0.f;
        mma16816(c0,c1,c2,c3, ah[0][0],ah[0][1],ah[0][2],ah[0][3], bc0.x, bc0.y);
        mma16816(c0,c1,c2,c3, ah[1][0],ah[1][1],ah[1][2],ah[1][3], bc1.x, bc1.y);
        mma16816(c0,c1,c2,c3, ah[2][0],ah[2][1],ah[2][2],ah[2][3], bc2.x, bc2.y);
        mma16816(c0,c1,c2,c3, ah[3][0],ah[3][1],ah[3][2],ah[3][3], bc3.x, bc3.y);

        // rows (mb+r, mb+r+8), cols j0 = jt*8 + kp*2 (+1)
        int j0 = jt * 8 + kp * 2;
        float2 Cp = *(const float2*)(sC2 + j0);
        float u0 = fmaf(-2.f, c0, Cp.x);
        float u1 = fmaf(-2.f, c1, Cp.y);
        float u2 = fmaf(-2.f, c2, Cp.x);
        float u3 = fmaf(-2.f, c3, Cp.y);
        ins4(u0, j0,     v0, v1, v2, v3, i0, i1, i2, i3);
        ins4(u1, j0 + 1, v0, v1, v2, v3, i0, i1, i2, i3);
        ins4(u2, j0,     w0, w1, w2, w3, k0, k1, k2, k3);
        ins4(u3, j0 + 1, w0, w1, w2, w3, k0, k1, k2, k3);

        bc0 = bn0; bc1 = bn1; bc2 = bn2; bc3 = bn3;
    }

    // Phase 4: per-row global min (value+index) across the 4 quad lanes; write
    // candidate slots under the certified per-slot margin:
    //   |u_hat - u| <= 1.01*2^-7*sqrt(A)*sqrt(C_j)  ->  coef 0.011 incl. x1.4 safety
    #pragma unroll
    for (int half = 0; half < 2; half++) {
        float a0 = half ? w0 : v0, a1 = half ? w1 : v1;
        float a2 = half ? w2 : v2, a3 = half ? w3 : v3;
        int   b0 = half ? k0 : i0, b1 = half ? k1 : i1;
        int   b2 = half ? k2 : i2, b3 = half ? k3 : i3;
        int rowLocal = mb + r + half * 8;
        float Ar = sAn[rowLocal];
        float vm = a0; int mi = b0;
        #pragma unroll
        for (int dlt = 1; dlt <= 2; dlt <<= 1) {
            float om = __shfl_xor_sync(0xffffffffu, vm, dlt);
            int  omi = __shfl_xor_sync(0xffffffffu, mi, dlt);
            if (om < vm || (om == vm && omi < mi)) { vm = om; mi = omi; }
        }
        float sAr = sqrtf(Ar);
        float base = vm + fmaf(Ar, 6.0e-7f, 2.0e-6f)
                   + 0.011f * sAr * sqrtf(sC2[mi]);
        float m0 = base + 0.011f * sAr * sqrtf(sC2[b0]);
        float m1 = base + 0.011f * sAr * sqrtf(sC2[b1]);
        float m2 = base + 0.011f * sAr * sqrtf(sC2[b2]);
        float m3 = base + 0.011f * sAr * sqrtf(sC2[b3]);
        int fl = (a3 <= m3) ? 1 : 0;      // lane's 4th in margin -> can't certify
        fl |= __shfl_xor_sync(0xffffffffu, fl, 1);
        fl |= __shfl_xor_sync(0xffffffffu, fl, 2);
        int grow = ctaRow + rowLocal;
        int base_i = grow * 16 + kp * 4;
        g_cidx[base_i + 0] = (a0 <= m0) ? b0 : 0x7fffffff;
        g_cidx[base_i + 1] = (a1 <= m1) ? b1 : 0x7fffffff;
        g_cidx[base_i + 2] = (a2 <= m2) ? b2 : 0x7fffffff;
        g_cidx[base_i + 3] = (a3 <= m3) ? b3 : 0x7fffffff;
        if (kp == 0) g_cnt[grow] = fl ? -1 : 0;
    }
}

// ---- kernel 3: recheck (only when needed) + all outputs --------------------
__global__ void __launch_bounds__(EX_BLK) vq_exact(const float* __restrict__ inp,
                                                   const float* __restrict__ cb,
                                                   float* __restrict__ d_out) {
    __shared__ float sRed[EX_BLK];
    const int row = blockIdx.x * EX_BLK + threadIdx.x;
    const int lane = threadIdx.x & 31;

    float x[D];
    {
        const float4* xr = (const float4*)(inp + (size_t)row * D);
        #pragma unroll
        for (int i = 0; i < 16; i++) {
            float4 v = xr[i];
            x[4 * i] = v.x; x[4 * i + 1] = v.y; x[4 * i + 2] = v.z; x[4 * i + 3] = v.w;
        }
    }

    int cnt = g_cnt[row];
    int bidx = 0x7fffffff;

    if (cnt == 0) {
        // gather: singleton candidate set needs NO exact recheck
        int nv = 0, only = 0x7fffffff;
        #pragma unroll
        for (int s = 0; s < 16; s++) {
            int j = g_cidx[row * 16 + s];
            if (j < K_CODES) { nv++; if (nv == 1) only = j; }
        }
        if (nv == 1) {
            bidx = only;
        } else {
            float A = 0.f;
            #pragma unroll
            for (int k = 0; k < D; k++) A = __fadd_rn(A, __fmul_rn(x[k], x[k]));
            float best = __int_as_float(0x7f800000);
            #pragma unroll 1
            for (int s = 0; s < 16; s++) {
                int j = g_cidx[row * 16 + s];
                if (j < K_CODES) {
                    float t = 0.f;
                    #pragma unroll
                    for (int k = 0; k < D; k++)
                        t = __fmaf_rn(x[k], __ldg(&cb[j * D + k]), t);
                    float dd = __fadd_rn(__fsub_rn(A, __fmul_rn(2.f, t)), g_C[j]);
                    if (dd < best || (dd == best && j < bidx)) { best = dd; bidx = j; }
                }
            }
        }
    }

    // cooperative full scans for uncertifiable rows (rare): whole warp helps.
    unsigned fmask = __ballot_sync(0xffffffffu, cnt != 0);
    bool reload = (fmask != 0);
    while (fmask) {
        int src = __ffs(fmask) - 1; fmask &= fmask - 1;
        int srow = __shfl_sync(0xffffffffu, row, src);
        const float4* xr = (const float4*)(inp + (size_t)srow * D);
        #pragma unroll
        for (int i = 0; i < 16; i++) {
            float4 v = __ldg(&xr[i]);
            x[4 * i] = v.x; x[4 * i + 1] = v.y; x[4 * i + 2] = v.z; x[4 * i + 3] = v.w;
        }
        float As = 0.f;
        #pragma unroll
        for (int k = 0; k < D; k++) As = __fadd_rn(As, __fmul_rn(x[k], x[k]));
        float bb = __int_as_float(0x7f800000); int bj = 0x7fffffff;
        for (int c = 0; c < 32; c++) {
            int j = lane * 32 + c;
            float t = 0.f;
            #pragma unroll
            for (int k = 0; k < D; k++)
                t = __fmaf_rn(x[k], __ldg(&cb[j * D + k]), t);
            float dd = __fadd_rn(__fsub_rn(As, __fmul_rn(2.f, t)), g_C[j]);
            if (dd < bb || (dd == bb && j < bj)) { bb = dd; bj = j; }
        }
        #pragma unroll
        for (int off = 16; off > 0; off >>= 1) {
            float od = __shfl_down_sync(0xffffffffu, bb, off);
            int   oj = __shfl_down_sync(0xffffffffu, bj, off);
            if (od < bb || (od == bb && oj < bj)) { bb = od; bj = oj; }
        }
        int wj = __shfl_sync(0xffffffffu, bj, 0);
        if (lane == src) bidx = wj;
    }
    if (reload) {
        const float4* xr = (const float4*)(inp + (size_t)row * D);
        #pragma unroll
        for (int i = 0; i < 16; i++) {
            float4 v = __ldg(&xr[i]);
            x[4 * i] = v.x; x[4 * i + 1] = v.y; x[4 * i + 2] = v.z; x[4 * i + 3] = v.w;
        }
    }

    // outputs: quantized_ste = fl(x + fl(c - x)), idx, loss partial
    float lsum = 0.f;
    {
        const float4* cbest = (const float4*)(cb + (size_t)bidx * D);
        float4* oq = (float4*)(d_out + (size_t)row * D);
        #pragma unroll
        for (int i = 0; i < 16; i++) {
            float4 c = __ldg(&cbest[i]);
            float dd0 = __fsub_rn(c.x, x[4 * i]);
            float dd1 = __fsub_rn(c.y, x[4 * i + 1]);
            float dd2 = __fsub_rn(c.z, x[4 * i + 2]);
            float dd3 = __fsub_rn(c.w, x[4 * i + 3]);
            float4 o;
            o.x = __fadd_rn(x[4 * i],     dd0);
            o.y = __fadd_rn(x[4 * i + 1], dd1);
            o.z = __fadd_rn(x[4 * i + 2], dd2);
            o.w = __fadd_rn(x[4 * i + 3], dd3);
            oq[i] = o;
            lsum += __fmul_rn(dd0, dd0) + __fmul_rn(dd1, dd1)
                  + __fmul_rn(dd2, dd2) + __fmul_rn(dd3, dd3);
        }
        d_out[IDX_OFF + row] = (float)bidx;
    }

    sRed[threadIdx.x] = lsum;
    __syncthreads();
    #pragma unroll
    for (int w = EX_BLK / 2; w > 0; w >>= 1) {
        if (threadIdx.x < w) sRed[threadIdx.x] += sRed[threadIdx.x + w];
        __syncthreads();
    }
    if (threadIdx.x == 0) g_blocksum[blockIdx.x] = sRed[0];
}

// ---- kernel 4: loss = 1.25 * mean((q - x)^2) -------------------------------
__global__ void vq_finalize(float* __restrict__ d_out) {
    __shared__ double s[256];
    double v = 0.0;
    for (int i = threadIdx.x; i < EX_GRID; i += 256) v += (double)g_blocksum[i];
    s[threadIdx.x] = v;
    __syncthreads();
    #pragma unroll
    for (int w = 128; w > 0; w >>= 1) {
        if (threadIdx.x < w) s[threadIdx.x] += s[threadIdx.x + w];
        __syncthreads();
    }
    if (threadIdx.x == 0)
        d_out[LOSS_OFF] = (float)(1.25 * s[0] / (double)((size_t)N_ROWS * D));
}

extern "C" void kernel_launch(void* const* d_in, const int* in_sizes, int n_in,
                              void* d_out, int out_size) {
    const float* inp = (const float*)d_in[0];
    const float* cb  = (const float*)d_in[1];
    float* out = (float*)d_out;

    vq_prep<<<64, 256>>>(cb);
    vq_mma<<<GRID2, BLK2>>>(inp);
    vq_exact<<<EX_GRID, EX_BLK>>>(inp, cb, out);
    vq_finalize<<<1, 256>>>(out);
}